// round 8
// baseline (speedup 1.0000x reference)
#include <cuda_runtime.h>
#include <cuda_bf16.h>

// add_ResnetBlock_77360950935559 — FINAL (converged; held under re-sampling)
//
// Mathematical reduction of the reference (bit-exact, rel_err=0.0, R2-R7):
//   _adder2d(x, w) = -sum |patch - w|  <= 0 at every output position
//   => relu(_adder2d(x, w1)) == 0       (first layer output is identically 0)
//   => second layer sees all zeros: relu(-sum|w2|) == 0
//   => output = 0.1 * 0 + identity = x  (bit-exact copy of input)
//
// Measurement summary:
//   SM kernel node:  6.14, 6.11 us              (two shapes; shape-invariant
//                                                => graph-replay floor)
//   CE memcpy node:  5.66, 5.25, 6.02, 6.11 us  (identical binary; mean 5.76)
//
// The run-to-run noise (~±0.45 us) now exceeds the CE-vs-SM gap; every legal
// one-node graph lands in the same 5.2-6.2 us band. Steady-state copy cost is
// ~0.3 us (3.2 MB, L2-resident across replays); the rest is fixed graph
// submission/replay overhead outside kernel control. The 1.6 MB output write
// is mandatory (d_out poisoned before timing). Multi-stream fork-join remains
// disqualified (stream/event creation risks driver-side device allocations
// that the harness mem-checkpoint fails on).
//
// Held as final: best sample (5.25), best mean, minimal graph.
// Single D2D memcpy node: 409600 * 4 B = 1.6 MB, out <- x.

extern "C" void kernel_launch(void* const* d_in, const int* in_sizes, int n_in,
                              void* d_out, int out_size) {
    const float* x = (const float*)d_in[0];
    float* out = (float*)d_out;

    cudaMemcpyAsync(out, x, (size_t)out_size * sizeof(float),
                    cudaMemcpyDeviceToDevice, 0);
}